// round 12
// baseline (speedup 1.0000x reference)
#include <cuda_runtime.h>
#include <math_constants.h>

// Until: out[b,t,x] = min(phi[b,t,x], max(psi[b,t,x], out[b,t-1,x])), out[-1] = -1e6.
// Single-pass chained scan (decoupled lookback). Monoid f(v)=min(A,max(B,v)):
//   compose (later∘earlier): A' = min(A2, max(B2, A1)), B' = max(B1, B2).
// R12: dual-chunk blocks — each block streams TWO same-tier chunks (batches b,
// b+32) before resolving either lookback, hiding the carry wait under streaming.

#define B_   64
#define HB_  32                 // half the batches
#define T_   8192
#define X_   32
#define TC_  256                // time steps per chunk
#define C_   (T_ / TC_)         // 32 chunks per batch
#define NCH_ (B_ * C_)          // 2048 chunks (flag entries)
#define NBK_ 1024               // blocks per launch (2 chunks each)
#define SL_  32                 // t-slices per chunk
#define PT_  (TC_ / SL_)        // 8 steps per thread
#define NW_  8                  // warps per block == lookback window size
#define SPW_ (SL_ / NW_)        // 4 slices per warp
#define LARGE_ 1.0e6f

__device__ float g_A[NCH_ * X_];   // chunk aggregate A
__device__ float g_Bv[NCH_ * X_];  // chunk aggregate B
__device__ float g_P[NCH_ * X_];   // chunk inclusive prefix value
__device__ int   g_flag[NCH_];     // epoch-tagged: 2e+1 aggregate, 2e+2 prefix
__device__ int   g_ticket;         // never reset; epoch = ticket / NBK_

__global__ void __launch_bounds__(256, 6) until_scan(const float* __restrict__ phi,
                                                     const float* __restrict__ psi,
                                                     float* __restrict__ out) {
    __shared__ float sA[2][SL_][X_];   // per-slice aggregate A (per half)
    __shared__ float sB[2][SL_][X_];   // per-slice aggregate B
    __shared__ float sWA[2][NW_][X_];  // per-warp fold
    __shared__ float sWB[2][NW_][X_];
    __shared__ float sGC[2][NW_][X_];  // carry entering each warp's slice group
    __shared__ float sFA[2][X_];       // chunk aggregate
    __shared__ float sFB[2][X_];
    __shared__ float wLA[NW_][X_];     // lookback window payload (A or P)
    __shared__ float wLB[NW_][X_];
    __shared__ int   wStat[NW_];       // 1 = PRE, 0 = AGG
    __shared__ int   s_done;
    __shared__ int   s_tic;

    const int tid = threadIdx.x;
    if (tid == 0) s_tic = atomicAdd(&g_ticket, 1);
    __syncthreads();
    const int traw = s_tic;
    const int e    = traw >> 10;          // epoch (NBK_ = 1024)
    const int v    = traw & (NBK_ - 1);
    const int c    = v >> 5;              // tier 0..31 (breadth-first)
    const int bp   = v & (HB_ - 1);       // batch pair index 0..31
    const int FLAG_AGG = 2 * e + 1;
    const int FLAG_PRE = 2 * e + 2;

    const int xg   = tid & 7;             // float4 group along x
    const int xq   = xg * 4;
    const int s    = tid >> 3;            // slice 0..31
    const int w    = tid >> 5;            // warp 0..7
    const int lane = tid & 31;

    const int bH[2] = { bp, bp + HB_ };   // two batches, same tier
    size_t baseH[2];
#pragma unroll
    for (int h = 0; h < 2; h++)
        baseH[h] = (size_t)bH[h] * T_ * X_ + (size_t)(c * TC_ + s * PT_) * X_ + xq;

    // ================= phase 1 x2: stream both chunks, publish both AGGs =================
#pragma unroll
    for (int h = 0; h < 2; h++) {
        const float4* pp = (const float4*)(phi + baseH[h]);
        const float4* qq = (const float4*)(psi + baseH[h]);

        float4 A  = make_float4( CUDART_INF_F,  CUDART_INF_F,  CUDART_INF_F,  CUDART_INF_F);
        float4 Bc = make_float4(-CUDART_INF_F, -CUDART_INF_F, -CUDART_INF_F, -CUDART_INF_F);
#pragma unroll
        for (int i = 0; i < PT_; i++) {
            float4 p = pp[i * (X_ / 4)];
            float4 q = qq[i * (X_ / 4)];
            A.x = fminf(p.x, fmaxf(q.x, A.x));  Bc.x = fmaxf(q.x, Bc.x);
            A.y = fminf(p.y, fmaxf(q.y, A.y));  Bc.y = fmaxf(q.y, Bc.y);
            A.z = fminf(p.z, fmaxf(q.z, A.z));  Bc.z = fmaxf(q.z, Bc.z);
            A.w = fminf(p.w, fmaxf(q.w, A.w));  Bc.w = fmaxf(q.w, Bc.w);
        }
        sA[h][s][xq + 0] = A.x;  sA[h][s][xq + 1] = A.y;  sA[h][s][xq + 2] = A.z;  sA[h][s][xq + 3] = A.w;
        sB[h][s][xq + 0] = Bc.x; sB[h][s][xq + 1] = Bc.y; sB[h][s][xq + 2] = Bc.z; sB[h][s][xq + 3] = Bc.w;
        __syncwarp();   // warp w's own slices only

        // fold level 1: warp w folds its 4 slices (lane = x)
        {
            float wA =  CUDART_INF_F;
            float wB = -CUDART_INF_F;
#pragma unroll
            for (int j = 0; j < SPW_; j++) {
                const int sl = w * SPW_ + j;
                wA = fminf(sA[h][sl][lane], fmaxf(sB[h][sl][lane], wA));
                wB = fmaxf(sB[h][sl][lane], wB);
            }
            sWA[h][w][lane] = wA;
            sWB[h][w][lane] = wB;
        }
        __syncthreads();

        // warp 0: fold level 2 + publish AGG (other warps continue to h=1 stream)
        if (tid < 32) {
            const int x = tid;
            float Ab =  CUDART_INF_F;
            float Bb = -CUDART_INF_F;
#pragma unroll
            for (int j = 0; j < NW_; j++) {
                Ab = fminf(sWA[h][j][x], fmaxf(sWB[h][j][x], Ab));
                Bb = fmaxf(sWB[h][j][x], Bb);
            }
            sFA[h][x] = Ab;
            sFB[h][x] = Bb;
            // chunk 0 never publishes AGG -> lookback can't cross batch boundary
            if (c > 0) {
                const int bc = bH[h] * C_ + c;
                g_A[bc * X_ + x]  = Ab;
                g_Bv[bc * X_ + x] = Bb;
                __threadfence();
                __syncwarp();
                if (x == 0) *(volatile int*)&g_flag[bc] = FLAG_AGG;
            }
        }
    }

    // ================= lookback x2: resolve carries, publish both PREs =================
#pragma unroll
    for (int h = 0; h < 2; h++) {
        const int bc = bH[h] * C_ + c;
        float vin = -LARGE_;               // meaningful in warp-0 lanes
        if (c > 0) {
            const int batch_lo = bH[h] * C_;
            int hi = bc - 1;
            float accA =  CUDART_INF_F;
            float accB = -CUDART_INF_F;
            while (true) {
                const int j = hi - w;      // warp w probes predecessor j
                if (j >= batch_lo) {
                    int f;
                    do { f = *(volatile int*)&g_flag[j]; } while (f < FLAG_AGG);
                    __threadfence();
                    const int isPre = (f >= FLAG_PRE);
                    wLA[w][lane] = isPre ? g_P[j * X_ + lane] : g_A[j * X_ + lane];
                    wLB[w][lane] = isPre ? -CUDART_INF_F      : g_Bv[j * X_ + lane];
                    if (lane == 0) wStat[w] = isPre;
                }
                __syncthreads();
                if (tid < 32) {
                    const int x = tid;
                    int found = 0;
#pragma unroll
                    for (int k = 0; k < NW_; k++) {
                        if (hi - k < batch_lo) break;
                        if (wStat[k]) {                 // PRE: resolve and stop
                            vin = fminf(accA, fmaxf(accB, wLA[k][x]));
                            found = 1;
                            break;
                        }
                        accA = fminf(accA, fmaxf(accB, wLA[k][x]));
                        accB = fmaxf(accB, wLB[k][x]);
                    }
                    if (x == 0) s_done = found;
                }
                __syncthreads();
                if (s_done) break;
                hi -= NW_;
            }
        }

        // warp 0: publish PRE first (shortest tier-to-tier latency), fill carries
        if (tid < 32) {
            const int x = tid;
            float pre = fminf(sFA[h][x], fmaxf(sFB[h][x], vin));
            g_P[bc * X_ + x] = pre;
            __threadfence();
            __syncwarp();
            if (x == 0) *(volatile int*)&g_flag[bc] = FLAG_PRE;

            float g = vin;
#pragma unroll
            for (int j = 0; j < NW_; j++) {
                sGC[h][j][x] = g;
                g = fminf(sWA[h][j][x], fmaxf(sWB[h][j][x], g));
            }
        }
        __syncthreads();   // protects wLA/wStat reuse (h=0 -> h=1) and sGC
    }

    // ================= phase 2 x2: reload (L2 hits), apply carry, stream out =================
#pragma unroll
    for (int h = 0; h < 2; h++) {
        float v0 = sGC[h][w][xq + 0];
        float v1 = sGC[h][w][xq + 1];
        float v2 = sGC[h][w][xq + 2];
        float v3 = sGC[h][w][xq + 3];
        for (int j = w * SPW_; j < s; j++) {
            v0 = fminf(sA[h][j][xq + 0], fmaxf(sB[h][j][xq + 0], v0));
            v1 = fminf(sA[h][j][xq + 1], fmaxf(sB[h][j][xq + 1], v1));
            v2 = fminf(sA[h][j][xq + 2], fmaxf(sB[h][j][xq + 2], v2));
            v3 = fminf(sA[h][j][xq + 3], fmaxf(sB[h][j][xq + 3], v3));
        }
        float4 vc = make_float4(v0, v1, v2, v3);

        const float4* pp = (const float4*)(phi + baseH[h]);
        const float4* qq = (const float4*)(psi + baseH[h]);
        float4* oo = (float4*)(out + baseH[h]);
#pragma unroll
        for (int i = 0; i < PT_; i++) {
            float4 p = __ldcs(&pp[i * (X_ / 4)]);
            float4 q = __ldcs(&qq[i * (X_ / 4)]);
            vc.x = fminf(p.x, fmaxf(q.x, vc.x));
            vc.y = fminf(p.y, fmaxf(q.y, vc.y));
            vc.z = fminf(p.z, fmaxf(q.z, vc.z));
            vc.w = fminf(p.w, fmaxf(q.w, vc.w));
            __stcs(&oo[i * (X_ / 4)], vc);
        }
    }
}

extern "C" void kernel_launch(void* const* d_in, const int* in_sizes, int n_in,
                              void* d_out, int out_size) {
    const float* phi = (const float*)d_in[0];
    const float* psi = (const float*)d_in[1];
    float* out = (float*)d_out;

    until_scan<<<NBK_, 256>>>(phi, psi, out);
}

// round 13
// speedup vs baseline: 1.3874x; 1.3874x over previous
#include <cuda_runtime.h>
#include <math_constants.h>

// Until: out[b,t,x] = min(phi[b,t,x], max(psi[b,t,x], out[b,t-1,x])), out[-1] = -1e6.
// Single-pass chained scan (decoupled lookback). Monoid f(v)=min(A,max(B,v)):
//   compose (later∘earlier): A' = min(A2, max(B2, A1)), B' = max(B1, B2).
// R13: R11 base + packed 64-bit publication protocol: tag|payload in ONE atomic
// word -> no threadfence, one L2 round trip per lookback hop.

#define B_   64
#define T_   8192
#define X_   32
#define TC_  256                // time steps per chunk
#define C_   (T_ / TC_)         // 32 chunks per batch
#define NB_  (B_ * C_)          // 2048 blocks
#define SL_  32                 // t-slices per block
#define PT_  (TC_ / SL_)        // 8 steps per thread
#define NW_  8                  // warps per block == lookback window size
#define SPW_ (SL_ / NW_)        // 4 slices per warp
#define LARGE_ 1.0e6f

typedef unsigned long long u64;

__device__ u64 g_Apk[NB_ * X_];   // (tag<<32)|bits(A)  chunk aggregate A
__device__ u64 g_Bpk[NB_ * X_];   // (tag<<32)|bits(B)  chunk aggregate B
__device__ u64 g_Ppk[NB_ * X_];   // (tag<<32)|bits(P)  chunk inclusive prefix
__device__ int g_ticket;          // never reset; epoch = ticket / NB_

__device__ __forceinline__ u64 pk(int tag, float v) {
    return ((u64)(unsigned)tag << 32) | (u64)__float_as_uint(v);
}

__global__ void __launch_bounds__(256, 6) until_scan(const float* __restrict__ phi,
                                                     const float* __restrict__ psi,
                                                     float* __restrict__ out) {
    __shared__ float sA[SL_][X_];     // per-slice aggregate A
    __shared__ float sB[SL_][X_];     // per-slice aggregate B
    __shared__ float sWA[NW_][X_];    // per-warp fold of its 4 slices
    __shared__ float sWB[NW_][X_];
    __shared__ float sGC[NW_][X_];    // carry entering each warp's slice group
    __shared__ float wLA[NW_][X_];    // lookback window payload (A or P)
    __shared__ float wLB[NW_][X_];    // lookback window payload (B)
    __shared__ int   wSt[NW_][X_];    // per-lane status: 1 = PRE, 0 = AGG
    __shared__ float sFA[X_];         // block aggregate A
    __shared__ float sFB[X_];         // block aggregate B
    __shared__ int   s_done;
    __shared__ int   s_tic;

    const int tid = threadIdx.x;
    if (tid == 0) s_tic = atomicAdd(&g_ticket, 1);
    __syncthreads();
    const int traw = s_tic;
    const int e    = traw >> 11;          // epoch (NB_ = 2048)
    const int v    = traw & (NB_ - 1);
    const int b    = v % B_;              // breadth-first over chunks
    const int c    = v / B_;
    const int bc   = b * C_ + c;
    const int FLAG_AGG = 2 * e + 1;
    const int FLAG_PRE = 2 * e + 2;

    const int xg   = tid & 7;             // float4 group along x
    const int xq   = xg * 4;
    const int s    = tid >> 3;            // slice 0..31
    const int w    = tid >> 5;            // warp 0..7
    const int lane = tid & 31;

    const size_t base = (size_t)b * T_ * X_ + (size_t)(c * TC_ + s * PT_) * X_ + xq;
    const float4* pp = (const float4*)(phi + base);
    const float4* qq = (const float4*)(psi + base);

    // ---------- phase 1: streaming slice aggregate (lines land in L2) ----------
    float4 A  = make_float4( CUDART_INF_F,  CUDART_INF_F,  CUDART_INF_F,  CUDART_INF_F);
    float4 Bc = make_float4(-CUDART_INF_F, -CUDART_INF_F, -CUDART_INF_F, -CUDART_INF_F);
#pragma unroll
    for (int i = 0; i < PT_; i++) {
        float4 p = pp[i * (X_ / 4)];
        float4 q = qq[i * (X_ / 4)];
        A.x = fminf(p.x, fmaxf(q.x, A.x));  Bc.x = fmaxf(q.x, Bc.x);
        A.y = fminf(p.y, fmaxf(q.y, A.y));  Bc.y = fmaxf(q.y, Bc.y);
        A.z = fminf(p.z, fmaxf(q.z, A.z));  Bc.z = fmaxf(q.z, Bc.z);
        A.w = fminf(p.w, fmaxf(q.w, A.w));  Bc.w = fmaxf(q.w, Bc.w);
    }
    sA[s][xq + 0] = A.x;  sA[s][xq + 1] = A.y;  sA[s][xq + 2] = A.z;  sA[s][xq + 3] = A.w;
    sB[s][xq + 0] = Bc.x; sB[s][xq + 1] = Bc.y; sB[s][xq + 2] = Bc.z; sB[s][xq + 3] = Bc.w;
    __syncwarp();   // slices 4w..4w+3 are written by warp w's own threads

    // ---------- fold level 1: warp w folds its 4 slices (lane = x) ----------
    {
        float wA =  CUDART_INF_F;
        float wB = -CUDART_INF_F;
#pragma unroll
        for (int j = 0; j < SPW_; j++) {
            const int sl = w * SPW_ + j;
            wA = fminf(sA[sl][lane], fmaxf(sB[sl][lane], wA));
            wB = fmaxf(sB[sl][lane], wB);
        }
        sWA[w][lane] = wA;
        sWB[w][lane] = wB;
    }
    __syncthreads();

    // ---------- warp 0: fold level 2 + publish AGG (packed, fence-free) ----------
    if (tid < 32) {
        const int x = tid;
        float Ab =  CUDART_INF_F;
        float Bb = -CUDART_INF_F;
#pragma unroll
        for (int j = 0; j < NW_; j++) {
            Ab = fminf(sWA[j][x], fmaxf(sWB[j][x], Ab));
            Bb = fmaxf(sWB[j][x], Bb);
        }
        sFA[x] = Ab;
        sFB[x] = Bb;
        // chunk 0 never publishes AGG -> lookback can't cross batch boundary
        if (c > 0) {
            const int gi = bc * X_ + x;
            *(volatile u64*)&g_Apk[gi] = pk(FLAG_AGG, Ab);
            *(volatile u64*)&g_Bpk[gi] = pk(FLAG_AGG, Bb);
        }
    }
    __syncthreads();

    // ---------- parallel-window lookback: 8 warps x 1 predecessor per round ----------
    float vin = -LARGE_;                  // meaningful in warp-0 lanes
    if (c > 0) {
        const int batch_lo = b * C_;      // chunk 0 of this batch (always reaches PRE)
        int hi = bc - 1;
        float accA =  CUDART_INF_F;       // warp-0 per-lane accumulators
        float accB = -CUDART_INF_F;
        int found = 0;
        while (true) {
            const int j = hi - w;         // warp w probes predecessor j (per-lane x)
            if (j >= batch_lo) {
                const int gi = j * X_ + lane;
                int st; float av, bv;
                while (true) {
                    u64 pv = *(volatile u64*)&g_Ppk[gi];
                    if ((int)(pv >> 32) == FLAG_PRE) {
                        st = 1; av = __uint_as_float((unsigned)pv); bv = -CUDART_INF_F;
                        break;
                    }
                    u64 aw = *(volatile u64*)&g_Apk[gi];
                    u64 bw = *(volatile u64*)&g_Bpk[gi];
                    if ((int)(aw >> 32) == FLAG_AGG && (int)(bw >> 32) == FLAG_AGG) {
                        st = 0; av = __uint_as_float((unsigned)aw); bv = __uint_as_float((unsigned)bw);
                        break;
                    }
                }
                wLA[w][lane] = av;
                wLB[w][lane] = bv;
                wSt[w][lane] = st;
            }
            __syncthreads();
            if (tid < 32) {
                const int x = tid;
                if (!found) {
#pragma unroll
                    for (int k = 0; k < NW_; k++) {
                        if (hi - k < batch_lo) break;     // below batch floor: stop
                        if (wSt[k][x]) {                  // PRE: resolve this lane
                            vin = fminf(accA, fmaxf(accB, wLA[k][x]));
                            found = 1;
                            break;
                        }
                        accA = fminf(accA, fmaxf(accB, wLA[k][x]));
                        accB = fmaxf(accB, wLB[k][x]);
                    }
                }
                int all = __all_sync(0xffffffffu, found);
                if (x == 0) s_done = all;
            }
            __syncthreads();
            if (s_done) break;
            hi -= NW_;
        }
    }

    // ---------- warp 0: publish PRE first (packed, fence-free), fill carries ----------
    if (tid < 32) {
        const int x = tid;
        float pre = fminf(sFA[x], fmaxf(sFB[x], vin));
        *(volatile u64*)&g_Ppk[bc * X_ + x] = pk(FLAG_PRE, pre);

        float g = vin;
#pragma unroll
        for (int j = 0; j < NW_; j++) {
            sGC[j][x] = g;
            g = fminf(sWA[j][x], fmaxf(sWB[j][x], g));
        }
    }
    __syncthreads();

    // ---------- per-thread slice carry (walk <=3 slices from warp-group carry) ----------
    float v0 = sGC[w][xq + 0];
    float v1 = sGC[w][xq + 1];
    float v2 = sGC[w][xq + 2];
    float v3 = sGC[w][xq + 3];
    for (int j = w * SPW_; j < s; j++) {
        v0 = fminf(sA[j][xq + 0], fmaxf(sB[j][xq + 0], v0));
        v1 = fminf(sA[j][xq + 1], fmaxf(sB[j][xq + 1], v1));
        v2 = fminf(sA[j][xq + 2], fmaxf(sB[j][xq + 2], v2));
        v3 = fminf(sA[j][xq + 3], fmaxf(sB[j][xq + 3], v3));
    }
    float4 vc = make_float4(v0, v1, v2, v3);

    // ---------- phase 2: reload (L2 hits), apply carry, stream out ----------
    float4* oo = (float4*)(out + base);
#pragma unroll
    for (int i = 0; i < PT_; i++) {
        float4 p = __ldcs(&pp[i * (X_ / 4)]);
        float4 q = __ldcs(&qq[i * (X_ / 4)]);
        vc.x = fminf(p.x, fmaxf(q.x, vc.x));
        vc.y = fminf(p.y, fmaxf(q.y, vc.y));
        vc.z = fminf(p.z, fmaxf(q.z, vc.z));
        vc.w = fminf(p.w, fmaxf(q.w, vc.w));
        __stcs(&oo[i * (X_ / 4)], vc);
    }
}

extern "C" void kernel_launch(void* const* d_in, const int* in_sizes, int n_in,
                              void* d_out, int out_size) {
    const float* phi = (const float*)d_in[0];
    const float* psi = (const float*)d_in[1];
    float* out = (float*)d_out;

    until_scan<<<NB_, 256>>>(phi, psi, out);
}